// round 1
// baseline (speedup 1.0000x reference)
#include <cuda_runtime.h>

#define NB 8
#define SS 2048
#define DD 800

// Scratch (allocation-free rule: __device__ globals)
__device__ float g_hW[(size_t)NB * SS * DD];       // 52.4 MB
__device__ float g_scores[(size_t)NB * SS * SS];   // 134 MB

// ----------------------------------------------------------------------------
// C[M,N] = A[M,K] @ B[K,N]   (A row-major K-contig, B row-major N-contig)
// 128x128 tile, BK=8, 8x8 per thread, 256 threads. N may be non-multiple of
// 128 (N=800); M and K are multiples of 128/8 for all call sites.
// ----------------------------------------------------------------------------
__global__ __launch_bounds__(256, 2)
void gemm_nn(const float* __restrict__ A, const float* __restrict__ Bm,
             float* __restrict__ C, int M, int N, int K,
             long long sA, long long sB, long long sC)
{
    A  += (long long)blockIdx.z * sA;
    Bm += (long long)blockIdx.z * sB;
    C  += (long long)blockIdx.z * sC;

    __shared__ float As[8][128];
    __shared__ float Bs[8][128];

    const int tid = threadIdx.x;
    const int tx = tid & 15;
    const int ty = tid >> 4;
    const int mBase = blockIdx.y * 128;
    const int nBase = blockIdx.x * 128;

    // A tile loads: 128 rows x 8 k, float4 per thread
    const int aRow = tid >> 1;
    const int aK   = (tid & 1) * 4;
    // B tile loads: 8 k-rows x 128 n, float4 per thread
    const int bK   = tid >> 5;
    const int bN   = (tid & 31) * 4;

    float acc[8][8];
#pragma unroll
    for (int i = 0; i < 8; ++i)
#pragma unroll
        for (int j = 0; j < 8; ++j) acc[i][j] = 0.f;

    const float* aPtr = A + (size_t)(mBase + aRow) * K + aK;

    for (int k0 = 0; k0 < K; k0 += 8) {
        float4 av = *(const float4*)(aPtr + k0);
        int gn = nBase + bN;                      // multiple of 4; N%4==0
        float4 bv = make_float4(0.f, 0.f, 0.f, 0.f);
        if (gn < N)
            bv = *(const float4*)(Bm + (size_t)(k0 + bK) * N + gn);

        As[aK + 0][aRow] = av.x;
        As[aK + 1][aRow] = av.y;
        As[aK + 2][aRow] = av.z;
        As[aK + 3][aRow] = av.w;
        *(float4*)&Bs[bK][bN] = bv;
        __syncthreads();

#pragma unroll
        for (int k = 0; k < 8; ++k) {
            float4 a0 = *(const float4*)&As[k][ty * 8];
            float4 a1 = *(const float4*)&As[k][ty * 8 + 4];
            float4 b0 = *(const float4*)&Bs[k][tx * 8];
            float4 b1 = *(const float4*)&Bs[k][tx * 8 + 4];
            float a[8] = {a0.x, a0.y, a0.z, a0.w, a1.x, a1.y, a1.z, a1.w};
            float b[8] = {b0.x, b0.y, b0.z, b0.w, b1.x, b1.y, b1.z, b1.w};
#pragma unroll
            for (int i = 0; i < 8; ++i)
#pragma unroll
                for (int j = 0; j < 8; ++j)
                    acc[i][j] = fmaf(a[i], b[j], acc[i][j]);
        }
        __syncthreads();
    }

#pragma unroll
    for (int i = 0; i < 8; ++i) {
        int row = mBase + ty * 8 + i;
#pragma unroll
        for (int jj = 0; jj < 2; ++jj) {
            int col = nBase + tx * 8 + jj * 4;
            if (col < N)
                *(float4*)(C + (size_t)row * N + col) =
                    make_float4(acc[i][jj * 4 + 0], acc[i][jj * 4 + 1],
                                acc[i][jj * 4 + 2], acc[i][jj * 4 + 3]);
        }
    }
}

// ----------------------------------------------------------------------------
// C[M,N] = A[M,K] @ B[N,K]^T   (both operands K-contiguous; NT GEMM)
// Used for scores (M=N=2048, K=800): all dims tile-aligned, no bounds checks.
// ----------------------------------------------------------------------------
__global__ __launch_bounds__(256, 2)
void gemm_nt(const float* __restrict__ A, const float* __restrict__ Bm,
             float* __restrict__ C, int M, int N, int K,
             long long sA, long long sB, long long sC)
{
    A  += (long long)blockIdx.z * sA;
    Bm += (long long)blockIdx.z * sB;
    C  += (long long)blockIdx.z * sC;

    __shared__ float As[8][128];
    __shared__ float Bs[8][128];

    const int tid = threadIdx.x;
    const int tx = tid & 15;
    const int ty = tid >> 4;
    const int mBase = blockIdx.y * 128;
    const int nBase = blockIdx.x * 128;

    const int aRow = tid >> 1;
    const int aK   = (tid & 1) * 4;
    const int bRow = tid >> 1;       // n index within tile
    const int bKo  = (tid & 1) * 4;

    float acc[8][8];
#pragma unroll
    for (int i = 0; i < 8; ++i)
#pragma unroll
        for (int j = 0; j < 8; ++j) acc[i][j] = 0.f;

    const float* aPtr = A + (size_t)(mBase + aRow) * K + aK;
    const float* bPtr = Bm + (size_t)(nBase + bRow) * K + bKo;

    for (int k0 = 0; k0 < K; k0 += 8) {
        float4 av = *(const float4*)(aPtr + k0);
        float4 bv = *(const float4*)(bPtr + k0);

        As[aK + 0][aRow] = av.x;
        As[aK + 1][aRow] = av.y;
        As[aK + 2][aRow] = av.z;
        As[aK + 3][aRow] = av.w;
        Bs[bKo + 0][bRow] = bv.x;
        Bs[bKo + 1][bRow] = bv.y;
        Bs[bKo + 2][bRow] = bv.z;
        Bs[bKo + 3][bRow] = bv.w;
        __syncthreads();

#pragma unroll
        for (int k = 0; k < 8; ++k) {
            float4 a0 = *(const float4*)&As[k][ty * 8];
            float4 a1 = *(const float4*)&As[k][ty * 8 + 4];
            float4 b0 = *(const float4*)&Bs[k][tx * 8];
            float4 b1 = *(const float4*)&Bs[k][tx * 8 + 4];
            float a[8] = {a0.x, a0.y, a0.z, a0.w, a1.x, a1.y, a1.z, a1.w};
            float b[8] = {b0.x, b0.y, b0.z, b0.w, b1.x, b1.y, b1.z, b1.w};
#pragma unroll
            for (int i = 0; i < 8; ++i)
#pragma unroll
                for (int j = 0; j < 8; ++j)
                    acc[i][j] = fmaf(a[i], b[j], acc[i][j]);
        }
        __syncthreads();
    }

#pragma unroll
    for (int i = 0; i < 8; ++i) {
        int row = mBase + ty * 8 + i;
#pragma unroll
        for (int jj = 0; jj < 2; ++jj) {
            int col = nBase + tx * 8 + jj * 4;
            *(float4*)(C + (size_t)row * N + col) =
                make_float4(acc[i][jj * 4 + 0], acc[i][jj * 4 + 1],
                            acc[i][jj * 4 + 2], acc[i][jj * 4 + 3]);
        }
    }
}

// ----------------------------------------------------------------------------
// In-place row softmax over length-SS rows. One block (256 threads) per row.
// ----------------------------------------------------------------------------
__global__ __launch_bounds__(256)
void softmax_rows(float* __restrict__ scores)
{
    __shared__ float red[8];
    const size_t row = blockIdx.x;
    float* p = scores + row * (size_t)SS;
    const int tid = threadIdx.x;

    // row max
    float m = -3.4e38f;
    for (int i = tid; i < SS; i += 256) m = fmaxf(m, p[i]);
#pragma unroll
    for (int o = 16; o; o >>= 1) m = fmaxf(m, __shfl_xor_sync(0xffffffffu, m, o));
    if ((tid & 31) == 0) red[tid >> 5] = m;
    __syncthreads();
    m = -3.4e38f;
#pragma unroll
    for (int i = 0; i < 8; ++i) m = fmaxf(m, red[i]);
    __syncthreads();

    // exp + sum
    float s = 0.f;
    for (int i = tid; i < SS; i += 256) {
        float e = __expf(p[i] - m);
        p[i] = e;
        s += e;
    }
#pragma unroll
    for (int o = 16; o; o >>= 1) s += __shfl_xor_sync(0xffffffffu, s, o);
    if ((tid & 31) == 0) red[tid >> 5] = s;
    __syncthreads();
    s = 0.f;
#pragma unroll
    for (int i = 0; i < 8; ++i) s += red[i];
    const float inv = 1.f / s;

    for (int i = tid; i < SS; i += 256) p[i] *= inv;
}

// ----------------------------------------------------------------------------
extern "C" void kernel_launch(void* const* d_in, const int* in_sizes, int n_in,
                              void* d_out, int out_size)
{
    const float* h = (const float*)d_in[0];   // [B,S,D]
    const float* W = (const float*)d_in[1];   // [D,D]
    float* out = (float*)d_out;               // [B,S,D]

    float *hW = nullptr, *scores = nullptr;
    cudaGetSymbolAddress((void**)&hW, g_hW);
    cudaGetSymbolAddress((void**)&scores, g_scores);

    // 1) hW = h @ W : M = B*S = 16384, N = 800, K = 800
    gemm_nn<<<dim3(7, 128, 1), 256>>>(h, W, hW, NB * SS, DD, DD, 0, 0, 0);

    // 2) scores[b] = hW[b] @ h[b]^T : M = N = 2048, K = 800, batched over z
    gemm_nt<<<dim3(16, 16, NB), 256>>>(hW, h, scores, SS, SS, DD,
                                       (long long)SS * DD,
                                       (long long)SS * DD,
                                       (long long)SS * SS);

    // 3) softmax over last axis, in place
    softmax_rows<<<NB * SS, 256>>>(scores);

    // 4) out[b] = P[b] @ h[b] : M = 2048, N = 800, K = 2048, batched over z
    gemm_nn<<<dim3(7, 16, NB), 256>>>(scores, h, out, SS, DD, SS,
                                      (long long)SS * SS,
                                      (long long)SS * DD,
                                      (long long)SS * DD);
}

// round 4
// speedup vs baseline: 2.2499x; 2.2499x over previous
#include <cuda_runtime.h>
#include <cuda_bf16.h>
#include <cstdint>

#define NB 8
#define SS 2048
#define DD 800

// ---------------------------------------------------------------------------
// Scratch (__device__ globals; no allocations allowed)
// ---------------------------------------------------------------------------
__device__ __nv_bfloat16 g_h_hi [(size_t)NB * SS * DD];
__device__ __nv_bfloat16 g_h_lo [(size_t)NB * SS * DD];
__device__ __nv_bfloat16 g_ht_hi[(size_t)NB * DD * SS];
__device__ __nv_bfloat16 g_ht_lo[(size_t)NB * DD * SS];
__device__ __nv_bfloat16 g_Wt_hi[(size_t)DD * DD];
__device__ __nv_bfloat16 g_Wt_lo[(size_t)DD * DD];
__device__ __nv_bfloat16 g_hW_hi[(size_t)NB * SS * DD];
__device__ __nv_bfloat16 g_hW_lo[(size_t)NB * SS * DD];
__device__ float         g_scores[(size_t)NB * SS * SS];
__device__ __nv_bfloat16 g_P_hi [(size_t)NB * SS * SS];
__device__ __nv_bfloat16 g_P_lo [(size_t)NB * SS * SS];

// ---------------------------------------------------------------------------
// PTX helpers (baseline sm_80+ ops only: cp.async, ldmatrix, mma.sync)
// ---------------------------------------------------------------------------
__device__ __forceinline__ uint32_t smem_u32(const void* p) {
    uint32_t a;
    asm("{ .reg .u64 t; cvta.to.shared.u64 t, %1; cvt.u32.u64 %0, t; }"
        : "=r"(a) : "l"(p));
    return a;
}

__device__ __forceinline__ void cpa16(uint32_t dst, const void* src, uint32_t sz) {
    asm volatile("cp.async.cg.shared.global [%0], [%1], 16, %2;"
                 :: "r"(dst), "l"(src), "r"(sz));
}

__device__ __forceinline__ void ldsm4(uint32_t* r, uint32_t addr) {
    asm volatile("ldmatrix.sync.aligned.m8n8.x4.shared.b16 {%0,%1,%2,%3}, [%4];"
                 : "=r"(r[0]), "=r"(r[1]), "=r"(r[2]), "=r"(r[3]) : "r"(addr));
}

__device__ __forceinline__ void ldsm2(uint32_t* r, uint32_t addr) {
    asm volatile("ldmatrix.sync.aligned.m8n8.x2.shared.b16 {%0,%1}, [%2];"
                 : "=r"(r[0]), "=r"(r[1]) : "r"(addr));
}

__device__ __forceinline__ void mma16816(float* c, const uint32_t* a, const uint32_t* b) {
    asm volatile(
        "mma.sync.aligned.m16n8k16.row.col.f32.bf16.bf16.f32 "
        "{%0,%1,%2,%3}, {%4,%5,%6,%7}, {%8,%9}, {%0,%1,%2,%3};"
        : "+f"(c[0]), "+f"(c[1]), "+f"(c[2]), "+f"(c[3])
        : "r"(a[0]), "r"(a[1]), "r"(a[2]), "r"(a[3]), "r"(b[0]), "r"(b[1]));
}

// ---------------------------------------------------------------------------
// Split-bf16 NT GEMM: C[M,N] = A[M,K] @ B[N,K]^T (both K-contiguous)
// A ~ Ahi+Alo, B ~ Bhi+Blo; C = AhiBhi + AhiBlo + AloBhi (fp32 accum)
// 128x128 tile, BK=32, 8 warps (2x4, 64x32 each), cp.async double buffer.
// K % 32 == 0 and M % 128 == 0 required (true for all call sites).
// ---------------------------------------------------------------------------
static constexpr int LDSB   = 80;            // 32 bf16 padded to 80 bytes
static constexpr int MATB   = 128 * LDSB;    // 10240 B per matrix tile
static constexpr int STAGEB = 4 * MATB;      // Ahi,Alo,Bhi,Blo = 40960 B
static constexpr int GEMM_SMEM = 2 * STAGEB; // 81920 B

template <bool SPLIT_OUT>
__global__ __launch_bounds__(256, 1)
void gemm_mma(const __nv_bfloat16* __restrict__ Ahi, const __nv_bfloat16* __restrict__ Alo,
              const __nv_bfloat16* __restrict__ Bhi, const __nv_bfloat16* __restrict__ Blo,
              float* __restrict__ C,
              __nv_bfloat16* __restrict__ Chi, __nv_bfloat16* __restrict__ Clo,
              int N, int K, int lda, int ldb, int ldc,
              long long sA, long long sB, long long sC)
{
    extern __shared__ char smem[];
    const uint32_t sb = smem_u32(smem);
    const int tid = threadIdx.x;
    const int wid = tid >> 5, lane = tid & 31;
    const int wm = wid >> 2, wn = wid & 3;          // 2 x 4 warp grid
    const int mBase = blockIdx.y * 128;
    const int nBase = blockIdx.x * 128;

    Ahi += (long long)blockIdx.z * sA;
    Alo += (long long)blockIdx.z * sA;
    Bhi += (long long)blockIdx.z * sB;
    Blo += (long long)blockIdx.z * sB;
    if (SPLIT_OUT) { Chi += (long long)blockIdx.z * sC; Clo += (long long)blockIdx.z * sC; }
    else           { C   += (long long)blockIdx.z * sC; }

    // per-thread ldmatrix base offsets (within a stage)
    const uint32_t aOff = (uint32_t)((wm * 64 + (lane & 15)) * LDSB + ((lane >> 4) * 16));
    const uint32_t bOff = (uint32_t)((wn * 32 + (lane & 7)) * LDSB + (((lane >> 3) & 1) * 16));

    float acc[4][4][4];
#pragma unroll
    for (int mt = 0; mt < 4; ++mt)
#pragma unroll
        for (int nt = 0; nt < 4; ++nt)
#pragma unroll
            for (int r = 0; r < 4; ++r) acc[mt][nt][r] = 0.f;

    const int NC = K >> 5;   // K / 32

    auto load_chunk = [&](int st, int c) {
        const uint32_t base = sb + (uint32_t)st * STAGEB;
        const int k0 = c * 32;
#pragma unroll
        for (int i = 0; i < 8; ++i) {
            const int u = tid + i * 256;             // 0..2047
            const int mat = u >> 9;                  // 0..3
            const int rem = u & 511;
            const int row = rem >> 2;                // 0..127
            const int kc = rem & 3;                  // 0..3 (16B chunks)
            const uint32_t dst = base + (uint32_t)(mat * MATB + row * LDSB + kc * 16);
            const int k = k0 + kc * 8;
            if (mat < 2) {
                const __nv_bfloat16* src = (mat ? Alo : Ahi) + (size_t)(mBase + row) * lda + k;
                cpa16(dst, src, 16u);
            } else {
                const int nr = nBase + row;
                const bool ok = nr < N;
                const __nv_bfloat16* src =
                    (mat == 3 ? Blo : Bhi) + (size_t)(ok ? nr : 0) * ldb + k;
                cpa16(dst, src, ok ? 16u : 0u);
            }
        }
        asm volatile("cp.async.commit_group;" ::: "memory");
    };

    load_chunk(0, 0);

    for (int c = 0; c < NC; ++c) {
        const int s = c & 1;
        if (c + 1 < NC) {
            load_chunk(s ^ 1, c + 1);
            asm volatile("cp.async.wait_group 1;" ::: "memory");
        } else {
            asm volatile("cp.async.wait_group 0;" ::: "memory");
        }
        __syncthreads();

        const uint32_t base = sb + (uint32_t)s * STAGEB;
#pragma unroll
        for (int ksb = 0; ksb <= 32; ksb += 32) {    // two k=16 steps (byte offsets)
            uint32_t ah[4][4], al[4][4], bh[4][2], bl[4][2];
#pragma unroll
            for (int mt = 0; mt < 4; ++mt) {
                ldsm4(ah[mt], base + aOff + (uint32_t)(mt * 16 * LDSB + ksb));
                ldsm4(al[mt], base + MATB + aOff + (uint32_t)(mt * 16 * LDSB + ksb));
            }
#pragma unroll
            for (int nt = 0; nt < 4; ++nt) {
                ldsm2(bh[nt], base + 2 * MATB + bOff + (uint32_t)(nt * 8 * LDSB + ksb));
                ldsm2(bl[nt], base + 3 * MATB + bOff + (uint32_t)(nt * 8 * LDSB + ksb));
            }
            // combo-major ordering: each acc tile revisited only after 15 others
#pragma unroll
            for (int mt = 0; mt < 4; ++mt)
#pragma unroll
                for (int nt = 0; nt < 4; ++nt)
                    mma16816(acc[mt][nt], ah[mt], bh[nt]);
#pragma unroll
            for (int mt = 0; mt < 4; ++mt)
#pragma unroll
                for (int nt = 0; nt < 4; ++nt)
                    mma16816(acc[mt][nt], ah[mt], bl[nt]);
#pragma unroll
            for (int mt = 0; mt < 4; ++mt)
#pragma unroll
                for (int nt = 0; nt < 4; ++nt)
                    mma16816(acc[mt][nt], al[mt], bh[nt]);
        }
        __syncthreads();
    }

    // epilogue: direct global stores from register fragments
    const int rowA = mBase + wm * 64 + (lane >> 2);
    const int colA = nBase + wn * 32 + (lane & 3) * 2;
#pragma unroll
    for (int mt = 0; mt < 4; ++mt) {
#pragma unroll
        for (int nt = 0; nt < 4; ++nt) {
            const int col = colA + nt * 8;
            if (col < N) {
#pragma unroll
                for (int half = 0; half < 2; ++half) {
                    const int row = rowA + mt * 16 + half * 8;
                    const float v0 = acc[mt][nt][half * 2 + 0];
                    const float v1 = acc[mt][nt][half * 2 + 1];
                    const size_t off = (size_t)row * ldc + col;
                    if (SPLIT_OUT) {
                        const __nv_bfloat16 h0 = __float2bfloat16(v0);
                        const __nv_bfloat16 h1 = __float2bfloat16(v1);
                        const __nv_bfloat16 l0 = __float2bfloat16(v0 - __bfloat162float(h0));
                        const __nv_bfloat16 l1 = __float2bfloat16(v1 - __bfloat162float(h1));
                        *(__nv_bfloat162*)(Chi + off) = __halves2bfloat162(h0, h1);
                        *(__nv_bfloat162*)(Clo + off) = __halves2bfloat162(l0, l1);
                    } else {
                        *(float2*)(C + off) = make_float2(v0, v1);
                    }
                }
            }
        }
    }
}

// ---------------------------------------------------------------------------
// fp32 -> (bf16 hi, bf16 lo) elementwise split
// ---------------------------------------------------------------------------
__global__ __launch_bounds__(256)
void split2(const float* __restrict__ x, __nv_bfloat16* __restrict__ hi,
            __nv_bfloat16* __restrict__ lo, size_t n)
{
    size_t i = (size_t)blockIdx.x * 256 + threadIdx.x;
    const size_t stride = (size_t)gridDim.x * 256;
    for (; i < n; i += stride) {
        const float v = x[i];
        const __nv_bfloat16 h = __float2bfloat16(v);
        hi[i] = h;
        lo[i] = __float2bfloat16(v - __bfloat162float(h));
    }
}

// ---------------------------------------------------------------------------
// Transpose fp32 [R,Cc] -> bf16 hi/lo [Cc,R] (batched over z)
// ---------------------------------------------------------------------------
__global__ __launch_bounds__(256)
void transpose_split(const float* __restrict__ in, __nv_bfloat16* __restrict__ ohi,
                     __nv_bfloat16* __restrict__ olo, int R, int Cc,
                     long long sIn, long long sOut)
{
    __shared__ float t[32][33];
    in  += (long long)blockIdx.z * sIn;
    ohi += (long long)blockIdx.z * sOut;
    olo += (long long)blockIdx.z * sOut;
    const int c0 = blockIdx.x * 32, r0 = blockIdx.y * 32;
    const int tx = threadIdx.x, ty = threadIdx.y;   // (32, 8)
#pragma unroll
    for (int i = 0; i < 32; i += 8)
        t[ty + i][tx] = in[(size_t)(r0 + ty + i) * Cc + c0 + tx];
    __syncthreads();
#pragma unroll
    for (int i = 0; i < 32; i += 8) {
        const float v = t[tx][ty + i];
        const __nv_bfloat16 h = __float2bfloat16(v);
        const size_t o = (size_t)(c0 + ty + i) * R + r0 + tx;
        ohi[o] = h;
        olo[o] = __float2bfloat16(v - __bfloat162float(h));
    }
}

// ---------------------------------------------------------------------------
// Row softmax (in: fp32 scores) -> bf16 hi/lo probability split
// ---------------------------------------------------------------------------
__global__ __launch_bounds__(256)
void softmax_rows(float* __restrict__ scores, __nv_bfloat16* __restrict__ phi,
                  __nv_bfloat16* __restrict__ plo)
{
    __shared__ float red[8];
    const size_t row = blockIdx.x;
    float* p = scores + row * (size_t)SS;
    __nv_bfloat16* oh = phi + row * (size_t)SS;
    __nv_bfloat16* ol = plo + row * (size_t)SS;
    const int tid = threadIdx.x;

    float m = -3.4e38f;
    for (int i = tid; i < SS; i += 256) m = fmaxf(m, p[i]);
#pragma unroll
    for (int o = 16; o; o >>= 1) m = fmaxf(m, __shfl_xor_sync(0xffffffffu, m, o));
    if ((tid & 31) == 0) red[tid >> 5] = m;
    __syncthreads();
    m = -3.4e38f;
#pragma unroll
    for (int i = 0; i < 8; ++i) m = fmaxf(m, red[i]);
    __syncthreads();

    float s = 0.f;
    for (int i = tid; i < SS; i += 256) {
        const float e = __expf(p[i] - m);
        p[i] = e;
        s += e;
    }
#pragma unroll
    for (int o = 16; o; o >>= 1) s += __shfl_xor_sync(0xffffffffu, s, o);
    if ((tid & 31) == 0) red[tid >> 5] = s;
    __syncthreads();
    s = 0.f;
#pragma unroll
    for (int i = 0; i < 8; ++i) s += red[i];
    const float inv = 1.f / s;

    for (int i = tid; i < SS; i += 256) {
        const float v = p[i] * inv;
        const __nv_bfloat16 h = __float2bfloat16(v);
        oh[i] = h;
        ol[i] = __float2bfloat16(v - __bfloat162float(h));
    }
}

// ---------------------------------------------------------------------------
extern "C" void kernel_launch(void* const* d_in, const int* in_sizes, int n_in,
                              void* d_out, int out_size)
{
    const float* h = (const float*)d_in[0];   // [B,S,D]
    const float* W = (const float*)d_in[1];   // [D,D]
    float* out = (float*)d_out;               // [B,S,D]

    __nv_bfloat16 *h_hi, *h_lo, *ht_hi, *ht_lo, *Wt_hi, *Wt_lo, *hW_hi, *hW_lo, *P_hi, *P_lo;
    float* scores;
    cudaGetSymbolAddress((void**)&h_hi, g_h_hi);
    cudaGetSymbolAddress((void**)&h_lo, g_h_lo);
    cudaGetSymbolAddress((void**)&ht_hi, g_ht_hi);
    cudaGetSymbolAddress((void**)&ht_lo, g_ht_lo);
    cudaGetSymbolAddress((void**)&Wt_hi, g_Wt_hi);
    cudaGetSymbolAddress((void**)&Wt_lo, g_Wt_lo);
    cudaGetSymbolAddress((void**)&hW_hi, g_hW_hi);
    cudaGetSymbolAddress((void**)&hW_lo, g_hW_lo);
    cudaGetSymbolAddress((void**)&scores, g_scores);
    cudaGetSymbolAddress((void**)&P_hi, g_P_hi);
    cudaGetSymbolAddress((void**)&P_lo, g_P_lo);

    cudaFuncSetAttribute(gemm_mma<false>, cudaFuncAttributeMaxDynamicSharedMemorySize, GEMM_SMEM);
    cudaFuncSetAttribute(gemm_mma<true>,  cudaFuncAttributeMaxDynamicSharedMemorySize, GEMM_SMEM);

    // pre-passes
    split2<<<8192, 256>>>(h, h_hi, h_lo, (size_t)NB * SS * DD);
    transpose_split<<<dim3(DD / 32, SS / 32, NB), dim3(32, 8)>>>(
        h, ht_hi, ht_lo, SS, DD, (long long)SS * DD, (long long)DD * SS);
    transpose_split<<<dim3(DD / 32, DD / 32, 1), dim3(32, 8)>>>(
        W, Wt_hi, Wt_lo, DD, DD, 0, 0);

    // 1) hW = h @ W : M=16384, N=800, K=800; B = Wt [N,K]; split output
    gemm_mma<true><<<dim3(7, 128, 1), 256, GEMM_SMEM>>>(
        h_hi, h_lo, Wt_hi, Wt_lo, nullptr, hW_hi, hW_lo,
        DD, DD, DD, DD, DD, 0, 0, 0);

    // 2) scores[b] = hW[b] @ h[b]^T : M=N=2048, K=800; fp32 output
    gemm_mma<false><<<dim3(16, 16, NB), 256, GEMM_SMEM>>>(
        hW_hi, hW_lo, h_hi, h_lo, scores, nullptr, nullptr,
        SS, DD, DD, DD, SS,
        (long long)SS * DD, (long long)SS * DD, (long long)SS * SS);

    // 3) softmax + split to bf16 hi/lo
    softmax_rows<<<NB * SS, 256>>>(scores, P_hi, P_lo);

    // 4) out[b] = P[b] @ h[b] : M=2048, N=800, K=2048; B = ht [N,K]; fp32 out
    gemm_mma<false><<<dim3(7, 16, NB), 256, GEMM_SMEM>>>(
        P_hi, P_lo, ht_hi, ht_lo, out, nullptr, nullptr,
        DD, SS, SS, SS, DD,
        (long long)SS * SS, (long long)DD * SS, (long long)SS * DD);
}